// round 15
// baseline (speedup 1.0000x reference)
#include <cuda_runtime.h>
#include <cuda_bf16.h>
#include <cuda_fp16.h>
#include <cstdint>

// Problem constants (fixed by the dataset)
#define IN_F   128
#define OUT_F  64
#define N_DIV  4
#define N_MAX  100000
#define E_MAX  1600000
#define NSEG_MAX (N_MAX * N_DIV)
#define NBLK_MAX 512

// Scratch: t[d][n][o] = norm[n] * (feature[n] . W[d][o]),  [4, N, 64] fp16 = 51.2 MB
__device__ __half t_buf[(size_t)N_DIV * N_MAX * OUT_F];
// CSR over segments seg = div*N + dst
__device__ int seg_count[NSEG_MAX];
__device__ int seg_start[NSEG_MAX + 1];
__device__ int seg_cursor[NSEG_MAX];
__device__ int sorted_row[E_MAX];   // src node id per edge (div implied by segment)
__device__ int blk_sum[NBLK_MAX];
// fp16 split feature: row layout [hi(128) | lo(128)], 51.2MB
__device__ __half f_half[(size_t)N_MAX * 256];
// fp16 weights (hi only — the 2-pass split drops the w-residual term)
__device__ __half w_half[N_DIV * OUT_F * IN_F];

// ---------------------------------------------------------------------------
// PTX helpers (sm_80-baseline features only: cp.async, ldmatrix, mma.sync)
// ---------------------------------------------------------------------------
__device__ __forceinline__ uint32_t smem_u32(const void* p) {
    uint32_t a;
    asm("{ .reg .u64 t; cvta.to.shared.u64 t, %1; cvt.u32.u64 %0, t; }" : "=r"(a) : "l"(p));
    return a;
}
__device__ __forceinline__ void cp16(uint32_t dst, const void* src, int valid) {
    int sz = valid ? 16 : 0;
    asm volatile("cp.async.cg.shared.global [%0], [%1], 16, %2;"
                 :: "r"(dst), "l"(src), "r"(sz));
}
#define CP_COMMIT() asm volatile("cp.async.commit_group;" ::: "memory")
#define CP_WAIT(n)  asm volatile("cp.async.wait_group %0;" :: "n"(n) : "memory")

__device__ __forceinline__ void ldsm_x4(uint32_t& r0, uint32_t& r1,
                                        uint32_t& r2, uint32_t& r3, uint32_t addr) {
    asm volatile("ldmatrix.sync.aligned.m8n8.x4.shared.b16 {%0,%1,%2,%3}, [%4];"
                 : "=r"(r0), "=r"(r1), "=r"(r2), "=r"(r3) : "r"(addr));
}
__device__ __forceinline__ void mma_f16(float* c, const uint32_t* a,
                                        uint32_t b0, uint32_t b1) {
    asm volatile("mma.sync.aligned.m16n8k16.row.col.f32.f16.f16.f32 "
                 "{%0,%1,%2,%3}, {%4,%5,%6,%7}, {%8,%9}, {%0,%1,%2,%3};"
                 : "+f"(c[0]), "+f"(c[1]), "+f"(c[2]), "+f"(c[3])
                 : "r"(a[0]), "r"(a[1]), "r"(a[2]), "r"(a[3]), "r"(b0), "r"(b1));
}
__device__ __forceinline__ uint32_t sw(uint32_t off) {
    return off ^ ((off >> 3) & 0x70);
}
__device__ __forceinline__ void acc_q(float* acc, const uint4& q) {
    float2 f0 = __half22float2(*(__half2*)&q.x);
    float2 f1 = __half22float2(*(__half2*)&q.y);
    float2 f2 = __half22float2(*(__half2*)&q.z);
    float2 f3 = __half22float2(*(__half2*)&q.w);
    acc[0] += f0.x; acc[1] += f0.y; acc[2] += f1.x; acc[3] += f1.y;
    acc[4] += f2.x; acc[5] += f2.y; acc[6] += f3.x; acc[7] += f3.y;
}

// ---------------------------------------------------------------------------
// Feature split conversion: f32 -> fp16 hi/lo, row layout [hi(128)|lo(128)].
// Memory-bound, massively parallel (this work was previously fused into the
// GEMM where it serialized at 1 CTA/SM — the round-14 bottleneck).
// ---------------------------------------------------------------------------
__global__ void convert_feat(const float* __restrict__ x, int count4)
{
    int i = blockIdx.x * blockDim.x + threadIdx.x;
    if (i >= count4) return;
    int n = i >> 5, c = i & 31;
    float4 v = ((const float4*)x)[i];
    __half h0 = __float2half_rn(v.x), h1 = __float2half_rn(v.y);
    __half h2 = __float2half_rn(v.z), h3 = __float2half_rn(v.w);
    __half l0 = __float2half_rn(v.x - __half2float(h0));
    __half l1 = __float2half_rn(v.y - __half2float(h1));
    __half l2 = __float2half_rn(v.z - __half2float(h2));
    __half l3 = __float2half_rn(v.w - __half2float(h3));
    __half2* hp = (__half2*)&f_half[(size_t)n * 256 + c * 4];
    __half2* lp = (__half2*)&f_half[(size_t)n * 256 + 128 + c * 4];
    hp[0] = __half2(h0, h1); hp[1] = __half2(h2, h3);
    lp[0] = __half2(l0, l1); lp[1] = __half2(l2, l3);
}

// ---------------------------------------------------------------------------
// W conversion: f32 -> fp16 (hi only), [4,64,128]
// ---------------------------------------------------------------------------
__global__ void convert_w(const float* __restrict__ x, int count4)
{
    int i = blockIdx.x * blockDim.x + threadIdx.x;
    if (i >= count4) return;
    float4 v = ((const float4*)x)[i];
    __half2* p = (__half2*)&w_half[(size_t)i * 4];
    p[0] = __floats2half2_rn(v.x, v.y);
    p[1] = __floats2half2_rn(v.z, v.w);
}

// ---------------------------------------------------------------------------
// mma.sync fp16 2-pass split GEMM, A-resident all-divisions, cp.async loads.
// Block: 128 nodes x ALL 4 divisions x 64 outs, 512 threads (16 warps).
// SMEM 96KB: A = 4 chunks x 16KB (xh0,xh1,xl0,xl1) via cp.async from f_half;
// B = 2 x 16KB (wh) double-buffered across divisions.
// Per division: 4 passes (xh0·wh0, xh1·wh1, xl0·wh0, xl1·wh1).
// Epilogue: norm-scale, fp16 store to t_buf.
// ---------------------------------------------------------------------------
__global__ void __launch_bounds__(512, 1) gemm_mma_kernel(
    const float* __restrict__ norm, int N)
{
    extern __shared__ __align__(16) char smem[];
    const uint32_t as_u = smem_u32(smem);          // A: 4 * 16384 = 64KB
    const uint32_t bs_u = as_u + 65536;            // B: 2 * 16384 = 32KB

    const int tid  = threadIdx.x;
    const int lane = tid & 31;
    const int wid  = tid >> 5;
    const int n0   = blockIdx.x * 128;
    const int warp_m = (wid >> 1) * 16;
    const int warp_n = (wid & 1) * 32;

    // ---- B loader: division d -> buffer buf (cp.async), wh only ----
    auto loadB = [&](int buf, int d) {
        uint32_t base = bs_u + buf * 16384;
        #pragma unroll
        for (int it = 0; it < 2; ++it) {           // 1024 16B units
            int id = tid + it * 512;
            int ch = id >> 9, rem = id & 511;
            int m = rem >> 3, u = rem & 7;
            const __half* src = w_half + ((size_t)(d * 64 + m)) * 128 + ch * 64 + u * 8;
            cp16(base + ch * 8192 + sw(m * 128 + u * 16), src, 1);
        }
    };

    // ---- A loader: all 4 chunks (xh0,xh1,xl0,xl1), zero-padded past N ----
    #pragma unroll
    for (int it = 0; it < 8; ++it) {               // 4096 16B units
        int id = tid + it * 512;
        int ch = id >> 10, rem = id & 1023;
        int m = rem >> 3, u = rem & 7;
        int n = n0 + m;
        int valid = (n < N);
        const __half* src =
            f_half + (size_t)(valid ? n : 0) * 256 + ch * 64 + u * 8;
        cp16(as_u + ch * 16384 + sw(m * 128 + u * 16), src, valid);
    }
    loadB(0, 0);
    CP_COMMIT();

    // pass tables: xh0·wh0, xh1·wh1, xl0·wh0, xl1·wh1
    const int ac[4] = { 0, 1, 2, 3 };
    const int bc[4] = { 0, 1, 0, 1 };

    float acc[4][4];
    #pragma unroll
    for (int j = 0; j < 4; ++j)
        #pragma unroll
        for (int k = 0; k < 4; ++k) acc[j][k] = 0.f;

    int buf = 0;
    for (int d = 0; d < N_DIV; ++d) {
        if (d < N_DIV - 1) {
            loadB(buf ^ 1, d + 1);
            CP_COMMIT();
            CP_WAIT(1);                     // A + B[d] landed; B[d+1] in flight
        } else {
            CP_WAIT(0);
        }
        __syncthreads();

        const uint32_t bbase0 = bs_u + buf * 16384;
        #pragma unroll
        for (int c = 0; c < 4; ++c) {
            const uint32_t abase = as_u + ac[c] * 16384;
            const uint32_t bbase = bbase0 + bc[c] * 8192;
            #pragma unroll
            for (int k16 = 0; k16 < 4; ++k16) {
                uint32_t a[4], b[2][4];
                {
                    int m = warp_m + (lane & 15);
                    int u = k16 * 2 + (lane >> 4);
                    ldsm_x4(a[0], a[1], a[2], a[3], abase + sw(m * 128 + u * 16));
                }
                #pragma unroll
                for (int ni = 0; ni < 2; ++ni) {
                    int n = warp_n + ni * 16 + (lane & 7) + ((lane >> 4) << 3);
                    int u = k16 * 2 + ((lane >> 3) & 1);
                    ldsm_x4(b[ni][0], b[ni][1], b[ni][2], b[ni][3],
                            bbase + sw(n * 128 + u * 16));
                }
                #pragma unroll
                for (int j = 0; j < 4; ++j) {
                    int ni = j >> 1, h = j & 1;
                    mma_f16(acc[j], a, b[ni][h * 2], b[ni][h * 2 + 1]);
                }
            }
        }
        __syncthreads();

        // ---- epilogue for division d: norm scale, fp16 store, clear acc ----
        {
            int r0 = n0 + warp_m + (lane >> 2);
            int r1 = r0 + 8;
            float nm0 = (r0 < N) ? norm[r0] : 0.f;
            float nm1 = (r1 < N) ? norm[r1] : 0.f;
            #pragma unroll
            for (int j = 0; j < 4; ++j) {
                int col = warp_n + j * 8 + (lane & 3) * 2;
                if (r0 < N) {
                    __half2 v = __floats2half2_rn(acc[j][0] * nm0, acc[j][1] * nm0);
                    *(__half2*)&t_buf[((size_t)d * N + r0) * OUT_F + col] = v;
                }
                if (r1 < N) {
                    __half2 v = __floats2half2_rn(acc[j][2] * nm1, acc[j][3] * nm1);
                    *(__half2*)&t_buf[((size_t)d * N + r1) * OUT_F + col] = v;
                }
                acc[j][0] = acc[j][1] = acc[j][2] = acc[j][3] = 0.f;
            }
        }
        buf ^= 1;
    }
}

// ---------------------------------------------------------------------------
// CSR build (div-major segments: seg = div*N + dst)
// ---------------------------------------------------------------------------
__global__ void zero_counts_kernel(int nseg)
{
    int i = blockIdx.x * blockDim.x + threadIdx.x;
    if (i < nseg) seg_count[i] = 0;
}

__global__ void hist_kernel(const int* __restrict__ dst,
                            const int* __restrict__ ediv, int E, int N)
{
    int e = blockIdx.x * blockDim.x + threadIdx.x;
    if (e >= E) return;
    int seg = ediv[e] * N + dst[e];
    atomicAdd(&seg_count[seg], 1);
}

__global__ void __launch_bounds__(1024) scan_block_sum(int nseg)
{
    __shared__ int wsum[32];
    int i = blockIdx.x * 1024 + threadIdx.x;
    int lane = threadIdx.x & 31;
    int wid  = threadIdx.x >> 5;
    int x = (i < nseg) ? seg_count[i] : 0;
    #pragma unroll
    for (int o = 16; o; o >>= 1) x += __shfl_down_sync(0xffffffffu, x, o);
    if (lane == 0) wsum[wid] = x;
    __syncthreads();
    if (wid == 0) {
        int y = wsum[lane];
        #pragma unroll
        for (int o = 16; o; o >>= 1) y += __shfl_down_sync(0xffffffffu, y, o);
        if (lane == 0) blk_sum[blockIdx.x] = y;
    }
}

__global__ void __launch_bounds__(512) scan_partials(int nblk, int nseg)
{
    __shared__ int sh[512];
    int tid = threadIdx.x;
    int v = (tid < nblk) ? blk_sum[tid] : 0;
    sh[tid] = v;
    __syncthreads();
    #pragma unroll
    for (int off = 1; off < 512; off <<= 1) {
        int u = (tid >= off) ? sh[tid - off] : 0;
        __syncthreads();
        sh[tid] += u;
        __syncthreads();
    }
    if (tid < nblk) blk_sum[tid] = sh[tid] - v;
    if (tid == nblk - 1) seg_start[nseg] = sh[tid];
}

__global__ void __launch_bounds__(1024) scan_final(int nseg)
{
    __shared__ int wsum[32];
    __shared__ int wbase[32];
    int i = blockIdx.x * 1024 + threadIdx.x;
    int lane = threadIdx.x & 31;
    int wid  = threadIdx.x >> 5;
    int v = (i < nseg) ? seg_count[i] : 0;
    int x = v;
    #pragma unroll
    for (int o = 1; o < 32; o <<= 1) {
        int u = __shfl_up_sync(0xffffffffu, x, o);
        if (lane >= o) x += u;
    }
    if (lane == 31) wsum[wid] = x;
    __syncthreads();
    if (wid == 0) {
        int y = wsum[lane];
        int z = y;
        #pragma unroll
        for (int o = 1; o < 32; o <<= 1) {
            int u = __shfl_up_sync(0xffffffffu, z, o);
            if (lane >= o) z += u;
        }
        wbase[lane] = z - y;
    }
    __syncthreads();
    if (i < nseg) {
        int off = blk_sum[blockIdx.x] + wbase[wid] + (x - v);
        seg_start[i]  = off;
        seg_cursor[i] = off;
    }
}

__global__ void fill_kernel(const int* __restrict__ src,
                            const int* __restrict__ dst,
                            const int* __restrict__ ediv, int E, int N)
{
    int e = blockIdx.x * blockDim.x + threadIdx.x;
    if (e >= E) return;
    int seg = ediv[e] * N + dst[e];
    int pos = atomicAdd(&seg_cursor[seg], 1);
    sorted_row[pos] = src[e];
}

// ---------------------------------------------------------------------------
// Gather-accumulate over fp16 t_buf: 8 threads per segment, each owns one
// uint4 (16B = 8 halves) of the 128B row. Unroll-4 for MLP=4.
// fp32 accumulation, fused norm*relu output (two float4 stores per thread).
// ---------------------------------------------------------------------------
__global__ void __launch_bounds__(256) gather_kernel(
    const float* __restrict__ norm,
    float* __restrict__ out, int nseg, int N)
{
    int g = blockIdx.x * 32 + (threadIdx.x >> 3);
    if (g >= nseg) return;
    int lane = threadIdx.x & 7;

    int dv  = g / N;            // division
    int dn  = g - dv * N;       // dst node

    int b  = seg_start[g];
    int e2 = seg_start[g + 1];

    const uint4* tb = (const uint4*)t_buf + (size_t)dv * N * 8;
    float acc[8] = { 0.f, 0.f, 0.f, 0.f, 0.f, 0.f, 0.f, 0.f };

    int i = b;
    for (; i + 4 <= e2; i += 4) {
        int r0 = sorted_row[i];
        int r1 = sorted_row[i + 1];
        int r2 = sorted_row[i + 2];
        int r3 = sorted_row[i + 3];
        uint4 q0 = __ldg(&tb[(size_t)r0 * 8 + lane]);
        uint4 q1 = __ldg(&tb[(size_t)r1 * 8 + lane]);
        uint4 q2 = __ldg(&tb[(size_t)r2 * 8 + lane]);
        uint4 q3 = __ldg(&tb[(size_t)r3 * 8 + lane]);
        acc_q(acc, q0); acc_q(acc, q1); acc_q(acc, q2); acc_q(acc, q3);
    }
    for (; i < e2; ++i) {
        int r0 = sorted_row[i];
        uint4 q0 = __ldg(&tb[(size_t)r0 * 8 + lane]);
        acc_q(acc, q0);
    }

    float nm = norm[dn];
    float4 o0, o1;
    o0.x = fmaxf(acc[0] * nm, 0.f);
    o0.y = fmaxf(acc[1] * nm, 0.f);
    o0.z = fmaxf(acc[2] * nm, 0.f);
    o0.w = fmaxf(acc[3] * nm, 0.f);
    o1.x = fmaxf(acc[4] * nm, 0.f);
    o1.y = fmaxf(acc[5] * nm, 0.f);
    o1.z = fmaxf(acc[6] * nm, 0.f);
    o1.w = fmaxf(acc[7] * nm, 0.f);
    float4* op = (float4*)out + (size_t)dn * 64 + dv * 16 + lane * 2;
    op[0] = o0;
    op[1] = o1;
}

// ---------------------------------------------------------------------------
extern "C" void kernel_launch(void* const* d_in, const int* in_sizes, int n_in,
                              void* d_out, int out_size)
{
    const float* feat = (const float*)d_in[0];
    const float* W    = (const float*)d_in[1];
    const float* norm = (const float*)d_in[2];
    const int*   src  = (const int*)d_in[3];
    const int*   dst  = (const int*)d_in[4];
    const int*   ediv = (const int*)d_in[5];
    float*       out  = (float*)d_out;

    const int N    = in_sizes[2];            // 100000
    const int E    = in_sizes[3];            // 1600000
    const int nseg = N * N_DIV;              // 400000
    const int nblk = (nseg + 1023) / 1024;   // 391

    // one-time infra (created on the correctness call, outside graph capture)
    static cudaStream_t s2 = nullptr;
    static cudaEvent_t ev_fork = nullptr, ev_join = nullptr, ev_w = nullptr;
    if (!s2) {
        cudaStreamCreateWithFlags(&s2, cudaStreamNonBlocking);
        cudaEventCreateWithFlags(&ev_fork, cudaEventDisableTiming);
        cudaEventCreateWithFlags(&ev_join, cudaEventDisableTiming);
        cudaEventCreateWithFlags(&ev_w, cudaEventDisableTiming);
        cudaFuncSetAttribute(gemm_mma_kernel,
                             cudaFuncAttributeMaxDynamicSharedMemorySize, 98304);
    }

    // ---- fork: convert_w + CSR build on s2 (kernel launches only) ----
    cudaEventRecord(ev_fork, 0);
    cudaStreamWaitEvent(s2, ev_fork, 0);

    int wc4 = (N_DIV * OUT_F * IN_F) / 4;
    convert_w<<<(wc4 + 255) / 256, 256, 0, s2>>>(W, wc4);
    cudaEventRecord(ev_w, s2);

    zero_counts_kernel<<<(nseg + 255) / 256, 256, 0, s2>>>(nseg);
    hist_kernel<<<(E + 255) / 256, 256, 0, s2>>>(dst, ediv, E, N);
    scan_block_sum<<<nblk, 1024, 0, s2>>>(nseg);
    scan_partials<<<1, 512, 0, s2>>>(nblk, nseg);
    scan_final<<<nblk, 1024, 0, s2>>>(nseg);
    fill_kernel<<<(E + 255) / 256, 256, 0, s2>>>(src, dst, ediv, E, N);
    cudaEventRecord(ev_join, s2);

    // ---- stream 0: feature convert -> GEMM (needs w_half via ev_w) ----
    int fc4 = (N * IN_F) / 4;
    convert_feat<<<(fc4 + 255) / 256, 256>>>(feat, fc4);

    cudaStreamWaitEvent(0, ev_w, 0);
    gemm_mma_kernel<<<(N + 127) / 128, 512, 98304>>>(norm, N);

    // ---- join: gather needs both t_buf (stream 0) and CSR (s2) ----
    cudaStreamWaitEvent(0, ev_join, 0);
    gather_kernel<<<(nseg + 31) / 32, 256>>>(norm, out, nseg, N);
}